// round 16
// baseline (speedup 1.0000x reference)
#include <cuda_runtime.h>
#include <cuda_fp16.h>
#include <math.h>

// ---------------- problem constants ----------------
#define NOPEN 64
#define NNIN  16
#define MAXN  65536
#define MAXE  4000000           // capacity for 2*nE incident entries
#define DTH   0.025f            // dt*H = (1/4)*0.1

// ---------------- device scratch ----------------
__device__ float    g_x[(size_t)MAXN * NOPEN];   // node features (f32)
__device__ __half2  g_p2[2][(size_t)MAXN * 32];  // ping-pong p = KN1 @ x (f16)
__device__ float    g_d2[MAXN];                  // 1/deg
__device__ int      g_deg[MAXN];
__device__ int      g_cnt[MAXN];                 // incident count
__device__ int      g_off[MAXN];                 // CSR offsets
__device__ int      g_cur[MAXN];                 // fill cursors
__device__ unsigned g_adj[MAXE];                 // (nbr<<16) | f16bits(+-w2)

// ---------------- kernel 0: init (deg/cnt) + x0 = relu(K1 @ xn) ------------
__global__ void __launch_bounds__(256)
init_x0_kernel(const float* __restrict__ xn, const float* __restrict__ K1,
               int nN) {
    __shared__ float sK[NNIN * NOPEN];       // sK[c*64+o] = K1[o][c]
    __shared__ float sX[NNIN][256];
    for (int idx = threadIdx.x; idx < NOPEN * NNIN; idx += blockDim.x) {
        int o = idx >> 4, c = idx & 15;
        sK[c * NOPEN + o] = K1[idx];
    }
    int n0 = blockIdx.x * 256;
    for (int idx = threadIdx.x; idx < NNIN * 256; idx += blockDim.x) {
        int c = idx >> 8, nn = idx & 255;
        int n = n0 + nn;
        sX[c][nn] = (n < nN) ? xn[(size_t)c * nN + n] : 0.f;
    }
    __syncthreads();

    int n = n0 + threadIdx.x;
    if (n >= nN) return;
    g_deg[n] = 1;                            // self loop
    g_cnt[n] = 0;

    float* dst = &g_x[(size_t)n * NOPEN];
#pragma unroll
    for (int half = 0; half < 2; half++) {
        float acc[32];
#pragma unroll
        for (int o = 0; o < 32; o++) acc[o] = 0.f;
#pragma unroll
        for (int c = 0; c < NNIN; c++) {
            float xc = sX[c][threadIdx.x];
#pragma unroll
            for (int o = 0; o < 32; o++)
                acc[o] += sK[c * NOPEN + half * 32 + o] * xc;
        }
#pragma unroll
        for (int o4 = 0; o4 < 8; o4++) {
            float4 r;
            r.x = fmaxf(acc[4 * o4 + 0], 0.f);
            r.y = fmaxf(acc[4 * o4 + 1], 0.f);
            r.z = fmaxf(acc[4 * o4 + 2], 0.f);
            r.w = fmaxf(acc[4 * o4 + 3], 0.f);
            ((float4*)dst)[half * 8 + o4] = r;
        }
    }
}

// ---------------- kernel 1: degree + incident counts ----------------
__global__ void count_kernel(const int* __restrict__ iInd,
                             const int* __restrict__ jInd, int nE) {
    int e = blockIdx.x * blockDim.x + threadIdx.x;
    if (e >= nE) return;
    int I = iInd[e], J = jInd[e];
    atomicAdd(&g_deg[J], 1);
    atomicAdd(&g_cnt[I], 1);
    atomicAdd(&g_cnt[J], 1);
}

// ---------------- kernel 2: single-block scan (g_cnt -> g_off/g_cur) + d2 --
__global__ void __launch_bounds__(1024)
scan_kernel(int nN) {
    __shared__ int sW[32];
    __shared__ int sT;
    __shared__ int sCarry;
    int tid = threadIdx.x;
    int lane = tid & 31;
    int wid = tid >> 5;
    if (tid == 0) sCarry = 0;
    __syncthreads();

    int nChunks = (nN + 1023) >> 10;
    for (int ch = 0; ch < nChunks; ch++) {
        int i = (ch << 10) + tid;
        int v = 0;
        if (i < nN) {
            v = g_cnt[i];
            g_d2[i] = 1.0f / (float)g_deg[i];
        }
        // warp inclusive scan
        int inc = v;
#pragma unroll
        for (int o = 1; o < 32; o <<= 1) {
            int u = __shfl_up_sync(0xffffffffu, inc, o);
            if (lane >= o) inc += u;
        }
        if (lane == 31) sW[wid] = inc;
        __syncthreads();
        if (wid == 0) {
            int t = sW[lane];
            int ti = t;
#pragma unroll
            for (int o = 1; o < 32; o <<= 1) {
                int u = __shfl_up_sync(0xffffffffu, ti, o);
                if (lane >= o) ti += u;
            }
            sW[lane] = ti - t;               // exclusive warp offsets
            if (lane == 31) sT = ti;         // chunk total
        }
        __syncthreads();
        int excl = sCarry + sW[wid] + inc - v;
        if (i < nN) { g_off[i] = excl; g_cur[i] = excl; }
        __syncthreads();                     // all reads of sCarry/sW done
        if (tid == 0) sCarry += sT;
        __syncthreads();
    }
}

// ---------------- kernel 3: fill CSR ----------------
__global__ void fill_kernel(const int* __restrict__ iInd,
                            const int* __restrict__ jInd, int nE) {
    int e = blockIdx.x * blockDim.x + threadIdx.x;
    if (e >= nE) return;
    int I = iInd[e], J = jInd[e];
    float w2 = g_d2[I] * g_d2[J];
    unsigned short hb = __half_as_ushort(__float2half(w2));
    int pI = atomicAdd(&g_cur[I], 1);
    g_adj[pI] = ((unsigned)J << 16) | hb;              // +w2: use fmax(t,0)
    int pJ = atomicAdd(&g_cur[J], 1);
    g_adj[pJ] = ((unsigned)I << 16) | hb | 0x8000u;    // -w2: use fmin(t,0)
}

// ---------------- kernel 4: pre p0 = f16(KN1 @ x) (warp per node) ----------
__global__ void __launch_bounds__(256)
pre_kernel(const float* __restrict__ KN1w, int nN) {
    __shared__ float sKp[64 * 66];           // sKp[k*66+o] = KN1[o][k]
    __shared__ float sRow[8][64];
    for (int idx = threadIdx.x; idx < 64 * 64; idx += blockDim.x) {
        int r = idx >> 6, c = idx & 63;
        sKp[c * 66 + r] = KN1w[idx];
    }
    __syncthreads();

    int lane = threadIdx.x & 31;
    int ws   = threadIdx.x >> 5;
    int n    = blockIdx.x * 8 + ws;
    if (n >= nN) return;
    int o0 = 2 * lane;

    float2 xv = *(const float2*)&g_x[(size_t)n * NOPEN + o0];
    sRow[ws][o0] = xv.x; sRow[ws][o0 + 1] = xv.y;
    __syncwarp();
    float p0 = 0.f, p1 = 0.f;
#pragma unroll 8
    for (int k = 0; k < 64; k++) {
        float xk = sRow[ws][k];
        float2 a = *(const float2*)&sKp[k * 66 + o0];
        p0 += a.x * xk;
        p1 += a.y * xk;
    }
    g_p2[0][(size_t)n * 32 + lane] = __floats2half2_rn(p0, p1);
}

// ---------------- fused layer: 4 nodes/warp, 8 lanes/node (R13 structure) --
__global__ void __launch_bounds__(256)
layer_kernel(const float* __restrict__ KN1w, const float* __restrict__ KC,
             float* __restrict__ out, int nN, int inbuf, int last) {
    __shared__ __half sKy[64 * 66];          // sKy[k*66+o] = KN1[k][o]
    __shared__ __half sKp[64 * 66];          // mid: KN1[o][k]; last: KC[o][i]
    __shared__ float sS[8][4][64];           // per-warp, per-node staging
    const float* P2 = last ? KC : KN1w;
    for (int idx = threadIdx.x; idx < 64 * 64; idx += blockDim.x) {
        int r = idx >> 6, c = idx & 63;
        sKy[r * 66 + c] = __float2half(KN1w[idx]);
        sKp[c * 66 + r] = __float2half(P2[idx]);
    }
    __syncthreads();

    const __half2* pin  = g_p2[inbuf];
    __half2*       pout = g_p2[inbuf ^ 1];

    int lane = threadIdx.x & 31;
    int ws   = threadIdx.x >> 5;
    int gi   = lane >> 3;                   // group (node) within warp, 0..3
    int li   = lane & 7;                    // lane within group
    int nBase = (blockIdx.x * 8 + ws) * 4;
    int n = nBase + gi;
    bool valid = (n < nN);

    int beg = 0, cnt = 0;
    if (valid) { beg = g_off[n]; cnt = g_cnt[n]; }

    // p_self: lane li holds dims 8li..8li+7 as 4 half2 (uint4)
    uint4 psu = make_uint4(0u, 0u, 0u, 0u);
    if (valid) psu = __ldg((const uint4*)(pin + (size_t)n * 32) + li);
    __half2 ps[4];
    ps[0] = *(__half2*)&psu.x; ps[1] = *(__half2*)&psu.y;
    ps[2] = *(__half2*)&psu.z; ps[3] = *(__half2*)&psu.w;

    int cmax = cnt;
#pragma unroll
    for (int o = 16; o; o >>= 1)
        cmax = max(cmax, __shfl_xor_sync(0xffffffffu, cmax, o));

    const __half2 zero2 = __float2half2_rn(0.f);
    __half2 acc[4];
#pragma unroll
    for (int i = 0; i < 4; i++) acc[i] = zero2;

    for (int t0 = 0; t0 < cmax; t0 += 16) {
        int ia = t0 + li, ib = t0 + 8 + li;
        unsigned va = (ia < cnt) ? __ldg(&g_adj[beg + ia]) : 0u;
        unsigned vb = (ib < cnt) ? __ldg(&g_adj[beg + ib]) : 0u;
#pragma unroll
        for (int h = 0; h < 2; h++) {
            unsigned src = h ? vb : va;
            unsigned vv[8];
            uint4 pbv[8];
#pragma unroll
            for (int k = 0; k < 8; k++)
                vv[k] = __shfl_sync(0xffffffffu, src, (gi << 3) | k);
#pragma unroll
            for (int k = 0; k < 8; k++)
                pbv[k] = __ldg((const uint4*)(pin + (size_t)(vv[k] >> 16) * 32) + li);
#pragma unroll
            for (int k = 0; k < 8; k++) {
                __half2 w2h = __half2half2(
                    __ushort_as_half((unsigned short)(vv[k] & 0x7fffu)));
                bool neg = (vv[k] & 0x8000u) != 0;
                __half2 t0h = __hsub2(ps[0], *(__half2*)&pbv[k].x);
                __half2 t1h = __hsub2(ps[1], *(__half2*)&pbv[k].y);
                __half2 t2h = __hsub2(ps[2], *(__half2*)&pbv[k].z);
                __half2 t3h = __hsub2(ps[3], *(__half2*)&pbv[k].w);
                __half2 d0 = neg ? __hmin2(t0h, zero2) : __hmax2(t0h, zero2);
                __half2 d1 = neg ? __hmin2(t1h, zero2) : __hmax2(t1h, zero2);
                __half2 d2 = neg ? __hmin2(t2h, zero2) : __hmax2(t2h, zero2);
                __half2 d3 = neg ? __hmin2(t3h, zero2) : __hmax2(t3h, zero2);
                acc[0] = __hfma2(d0, w2h, acc[0]);
                acc[1] = __hfma2(d1, w2h, acc[1]);
                acc[2] = __hfma2(d2, w2h, acc[2]);
                acc[3] = __hfma2(d3, w2h, acc[3]);
            }
        }
    }

#pragma unroll
    for (int i = 0; i < 4; i++) {
        float2 f = __half22float2(acc[i]);
        *(float2*)&sS[ws][gi][li * 8 + 2 * i] = f;
    }
    __syncwarp();

    int o0 = 2 * lane;
#pragma unroll
    for (int q = 0; q < 4; q++) {
        int nq = nBase + q;
        if (nq >= nN) break;
        float y0 = 0.f, y1 = 0.f;
#pragma unroll 8
        for (int k = 0; k < 64; k++) {
            float sk = sS[ws][q][k];
            float2 av = __half22float2(*(const __half2*)&sKy[k * 66 + o0]);
            y0 += av.x * sk;
            y1 += av.y * sk;
        }
        size_t off = (size_t)nq * NOPEN + o0;
        float2 xv = *(const float2*)&g_x[off];
        xv.x -= DTH * y0;
        xv.y -= DTH * y1;

        __syncwarp();
        sS[ws][q][o0] = xv.x; sS[ws][q][o0 + 1] = xv.y;
        __syncwarp();
        float v0 = 0.f, v1 = 0.f;
#pragma unroll 8
        for (int k = 0; k < 64; k++) {
            float xk = sS[ws][q][k];
            float2 av = __half22float2(*(const __half2*)&sKp[k * 66 + o0]);
            v0 += av.x * xk;
            v1 += av.y * xk;
        }

        if (!last) {
            *(float2*)&g_x[off] = xv;
            pout[(size_t)nq * 32 + lane] = __floats2half2_rn(v0, v1);
        } else {
            float m = fmaxf(v0, v1);
#pragma unroll
            for (int o = 16; o; o >>= 1)
                m = fmaxf(m, __shfl_xor_sync(0xffffffffu, m, o));
            float s = expf(v0 - m) + expf(v1 - m);
#pragma unroll
            for (int o = 16; o; o >>= 1)
                s += __shfl_xor_sync(0xffffffffu, s, o);
            float lse = m + logf(s);
            float2 r;
            r.x = v0 - lse;
            r.y = v1 - lse;
            *(float2*)&out[(size_t)nq * NOPEN + o0] = r;
        }
    }
}

// ---------------- launch ----------------
extern "C" void kernel_launch(void* const* d_in, const int* in_sizes, int n_in,
                              void* d_out, int out_size) {
    const float* xn   = (const float*)d_in[0];
    const int*   iInd = (const int*)d_in[1];
    const int*   jInd = (const int*)d_in[2];
    int base = 3;
    if (n_in >= 7 && in_sizes[3] == 1) base = 4;
    const float* K1  = (const float*)d_in[base];
    const float* KN1 = (const float*)d_in[base + 1];
    const float* KC  = (const float*)d_in[base + 2];

    int nN = in_sizes[0] / NNIN;
    int nE = in_sizes[1];

    int nodeBlocks8 = (nN + 7) / 8;
    int layerBlocks = (nN + 31) / 32;
    int nb256 = (nN + 255) / 256;
    int eb256 = (nE + 255) / 256;

    // launch order fixed so ncu (-s 5 -c 1) captures layer 0
    init_x0_kernel<<<nb256, 256>>>(xn, K1, nN);          // 0
    count_kernel<<<eb256, 256>>>(iInd, jInd, nE);        // 1
    scan_kernel<<<1, 1024>>>(nN);                        // 2  (+d2)
    fill_kernel<<<eb256, 256>>>(iInd, jInd, nE);         // 3
    pre_kernel<<<nodeBlocks8, 256>>>(KN1, nN);           // 4
    for (int l = 0; l < 4; l++)                          // 5,6,7,8
        layer_kernel<<<layerBlocks, 256>>>(KN1, KC, (float*)d_out, nN, l & 1,
                                           l == 3 ? 1 : 0);
}

// round 17
// speedup vs baseline: 1.0688x; 1.0688x over previous
#include <cuda_runtime.h>
#include <cuda_fp16.h>
#include <math.h>

// ---------------- problem constants ----------------
#define NOPEN 64
#define NNIN  16
#define MAXN  65536
#define MAXE  4000000           // capacity for 2*nE incident entries
#define DTH   0.025f            // dt*H = (1/4)*0.1
#define SCAN_B 256

// ---------------- device scratch ----------------
__device__ float    g_x[(size_t)MAXN * NOPEN];   // node features (f32)
__device__ __half2  g_p2[2][(size_t)MAXN * 32];  // ping-pong p = KN1 @ x (f16)
__device__ float    g_d2[MAXN];                  // 1/deg
__device__ int      g_deg[MAXN];
__device__ int      g_cnt[MAXN];                 // incident count
__device__ int      g_off[MAXN];                 // CSR offsets
__device__ int      g_cur[MAXN];                 // fill cursors
__device__ unsigned g_adj[MAXE];                 // (nbr<<16) | f16bits(+-w2)
__device__ int      g_bsum[256];
__device__ int      g_bpre[256];

// ---------------- kernel: init (deg/cnt) + x0 = relu(K1 @ xn) --------------
__global__ void __launch_bounds__(256)
init_x0_kernel(const float* __restrict__ xn, const float* __restrict__ K1,
               int nN) {
    __shared__ float sK[NNIN * NOPEN];       // sK[c*64+o] = K1[o][c]
    __shared__ float sX[NNIN][256];
    for (int idx = threadIdx.x; idx < NOPEN * NNIN; idx += blockDim.x) {
        int o = idx >> 4, c = idx & 15;
        sK[c * NOPEN + o] = K1[idx];
    }
    int n0 = blockIdx.x * 256;
    for (int idx = threadIdx.x; idx < NNIN * 256; idx += blockDim.x) {
        int c = idx >> 8, nn = idx & 255;
        int n = n0 + nn;
        sX[c][nn] = (n < nN) ? xn[(size_t)c * nN + n] : 0.f;
    }
    __syncthreads();

    int n = n0 + threadIdx.x;
    if (n >= nN) return;
    g_deg[n] = 1;                            // self loop
    g_cnt[n] = 0;

    float* dst = &g_x[(size_t)n * NOPEN];
#pragma unroll
    for (int half = 0; half < 2; half++) {
        float acc[32];
#pragma unroll
        for (int o = 0; o < 32; o++) acc[o] = 0.f;
#pragma unroll
        for (int c = 0; c < NNIN; c++) {
            float xc = sX[c][threadIdx.x];
#pragma unroll
            for (int o = 0; o < 32; o++)
                acc[o] += sK[c * NOPEN + half * 32 + o] * xc;
        }
#pragma unroll
        for (int o4 = 0; o4 < 8; o4++) {
            float4 r;
            r.x = fmaxf(acc[4 * o4 + 0], 0.f);
            r.y = fmaxf(acc[4 * o4 + 1], 0.f);
            r.z = fmaxf(acc[4 * o4 + 2], 0.f);
            r.w = fmaxf(acc[4 * o4 + 3], 0.f);
            ((float4*)dst)[half * 8 + o4] = r;
        }
    }
}

// ---------------- degree + incident counts ----------------
__global__ void count_kernel(const int* __restrict__ iInd,
                             const int* __restrict__ jInd, int nE) {
    int e = blockIdx.x * blockDim.x + threadIdx.x;
    if (e >= nE) return;
    int I = iInd[e], J = jInd[e];
    atomicAdd(&g_deg[J], 1);
    atomicAdd(&g_cnt[I], 1);
    atomicAdd(&g_cnt[J], 1);
}

// ---------------- 3-phase scan (coalesced) + d2 ----------------
__global__ void __launch_bounds__(SCAN_B)
scanA_kernel(int nPad4, int nN) {
    __shared__ int sSum[SCAN_B];
    int idx4 = blockIdx.x * SCAN_B + threadIdx.x;
    int4 v = (idx4 < nPad4) ? ((const int4*)g_cnt)[idx4] : make_int4(0, 0, 0, 0);
    sSum[threadIdx.x] = v.x + v.y + v.z + v.w;
    // fold in d2 computation (coalesced)
    int i = blockIdx.x * SCAN_B + threadIdx.x;
    for (int base = 0; base < 4; base++) {
        int ii = base * gridDim.x * SCAN_B + i;
        if (ii < nN) g_d2[ii] = 1.0f / (float)g_deg[ii];
    }
    __syncthreads();
    for (int d = SCAN_B / 2; d; d >>= 1) {
        if (threadIdx.x < d) sSum[threadIdx.x] += sSum[threadIdx.x + d];
        __syncthreads();
    }
    if (threadIdx.x == 0) g_bsum[blockIdx.x] = sSum[0];
}
__global__ void __launch_bounds__(256)
scanB_kernel(int nBlocks) {
    __shared__ int sV[256];
    int t = threadIdx.x;
    sV[t] = (t < nBlocks) ? g_bsum[t] : 0;
    __syncthreads();
    for (int d = 1; d < 256; d <<= 1) {
        int v = (t >= d) ? sV[t - d] : 0;
        __syncthreads();
        sV[t] += v;
        __syncthreads();
    }
    if (t < nBlocks) g_bpre[t] = sV[t] - g_bsum[t];
}
__global__ void __launch_bounds__(SCAN_B)
scanC_kernel(int nPad4) {
    __shared__ int sV[SCAN_B];
    int idx4 = blockIdx.x * SCAN_B + threadIdx.x;
    int4 v = (idx4 < nPad4) ? ((const int4*)g_cnt)[idx4] : make_int4(0, 0, 0, 0);
    int tsum = v.x + v.y + v.z + v.w;
    sV[threadIdx.x] = tsum;
    __syncthreads();
    for (int d = 1; d < SCAN_B; d <<= 1) {
        int u = (threadIdx.x >= d) ? sV[threadIdx.x - d] : 0;
        __syncthreads();
        sV[threadIdx.x] += u;
        __syncthreads();
    }
    int base = g_bpre[blockIdx.x] + sV[threadIdx.x] - tsum;
    if (idx4 < nPad4) {
        int4 o;
        o.x = base;
        o.y = base + v.x;
        o.z = base + v.x + v.y;
        o.w = base + v.x + v.y + v.z;
        ((int4*)g_off)[idx4] = o;
        ((int4*)g_cur)[idx4] = o;
    }
}

__global__ void fill_kernel(const int* __restrict__ iInd,
                            const int* __restrict__ jInd, int nE) {
    int e = blockIdx.x * blockDim.x + threadIdx.x;
    if (e >= nE) return;
    int I = iInd[e], J = jInd[e];
    float w2 = g_d2[I] * g_d2[J];
    unsigned short hb = __half_as_ushort(__float2half(w2));
    int pI = atomicAdd(&g_cur[I], 1);
    g_adj[pI] = ((unsigned)J << 16) | hb;              // +w2: use fmax(t,0)
    int pJ = atomicAdd(&g_cur[J], 1);
    g_adj[pJ] = ((unsigned)I << 16) | hb | 0x8000u;    // -w2: use fmin(t,0)
}

// ---------------- pre: p0 = f16(KN1 @ x) (warp per node) ----------------
__global__ void __launch_bounds__(256)
pre_kernel(const float* __restrict__ KN1w, int nN) {
    __shared__ float sKp[64 * 66];           // sKp[k*66+o] = KN1[o][k]
    __shared__ float sRow[8][64];
    for (int idx = threadIdx.x; idx < 64 * 64; idx += blockDim.x) {
        int r = idx >> 6, c = idx & 63;
        sKp[c * 66 + r] = KN1w[idx];
    }
    __syncthreads();

    int lane = threadIdx.x & 31;
    int ws   = threadIdx.x >> 5;
    int n    = blockIdx.x * 8 + ws;
    if (n >= nN) return;
    int o0 = 2 * lane;

    float2 xv = *(const float2*)&g_x[(size_t)n * NOPEN + o0];
    sRow[ws][o0] = xv.x; sRow[ws][o0 + 1] = xv.y;
    __syncwarp();
    float p0 = 0.f, p1 = 0.f;
#pragma unroll 8
    for (int k = 0; k < 64; k++) {
        float xk = sRow[ws][k];
        float2 a = *(const float2*)&sKp[k * 66 + o0];
        p0 += a.x * xk;
        p1 += a.y * xk;
    }
    g_p2[0][(size_t)n * 32 + lane] = __floats2half2_rn(p0, p1);
}

// ---------------- fused layer: 2 warps per 4-node quad ----------------
// gather: warp-pair splits tiles (t0 = halfId*16, step 32) -> partials in
// sS[pair][halfId][node]; pair named-barrier; epilogue: even warp nodes 0-1,
// odd warp nodes 2-3, summing both partial buffers on the fly.
__global__ void __launch_bounds__(256)
layer_kernel(const float* __restrict__ KN1w, const float* __restrict__ KC,
             float* __restrict__ out, int nN, int inbuf, int last) {
    __shared__ __half sKy[64 * 66];          // sKy[k*66+o] = KN1[k][o]
    __shared__ __half sKp[64 * 66];          // mid: KN1[o][k]; last: KC[o][i]
    __shared__ float sS[4][2][4][64];        // [pair][halfId][node][dim]
    const float* P2 = last ? KC : KN1w;
    for (int idx = threadIdx.x; idx < 64 * 64; idx += blockDim.x) {
        int r = idx >> 6, c = idx & 63;
        sKy[r * 66 + c] = __float2half(KN1w[idx]);
        sKp[c * 66 + r] = __float2half(P2[idx]);
    }
    __syncthreads();

    const __half2* pin  = g_p2[inbuf];
    __half2*       pout = g_p2[inbuf ^ 1];

    int lane = threadIdx.x & 31;
    int ws   = threadIdx.x >> 5;
    int pair = ws >> 1;                     // 0..3 (node-quad within block)
    int halfId = ws & 1;                    // which warp of the pair
    int gi   = lane >> 3;                   // node within quad, 0..3
    int li   = lane & 7;                    // lane within node-group
    int nBase = (blockIdx.x * 4 + pair) * 4;
    int n = nBase + gi;
    bool valid = (n < nN);

    int beg = 0, cnt = 0;
    if (valid) { beg = g_off[n]; cnt = g_cnt[n]; }

    // p_self: lane li holds dims 8li..8li+7 as 4 half2 (uint4)
    uint4 psu = make_uint4(0u, 0u, 0u, 0u);
    if (valid) psu = __ldg((const uint4*)(pin + (size_t)n * 32) + li);
    __half2 ps[4];
    ps[0] = *(__half2*)&psu.x; ps[1] = *(__half2*)&psu.y;
    ps[2] = *(__half2*)&psu.z; ps[3] = *(__half2*)&psu.w;

    int cmax = cnt;
#pragma unroll
    for (int o = 16; o; o >>= 1)
        cmax = max(cmax, __shfl_xor_sync(0xffffffffu, cmax, o));

    const __half2 zero2 = __float2half2_rn(0.f);
    __half2 acc[4];
#pragma unroll
    for (int i = 0; i < 4; i++) acc[i] = zero2;

    // this warp handles tiles t0 = halfId*16, halfId*16+32, ...
    for (int t0 = halfId * 16; t0 < cmax; t0 += 32) {
        int ia = t0 + li, ib = t0 + 8 + li;
        unsigned va = (ia < cnt) ? __ldg(&g_adj[beg + ia]) : 0u;
        unsigned vb = (ib < cnt) ? __ldg(&g_adj[beg + ib]) : 0u;
#pragma unroll
        for (int h = 0; h < 2; h++) {
            unsigned src = h ? vb : va;
            unsigned vv[8];
            uint4 pbv[8];
#pragma unroll
            for (int k = 0; k < 8; k++)
                vv[k] = __shfl_sync(0xffffffffu, src, (gi << 3) | k);
#pragma unroll
            for (int k = 0; k < 8; k++)
                pbv[k] = __ldg((const uint4*)(pin + (size_t)(vv[k] >> 16) * 32) + li);
#pragma unroll
            for (int k = 0; k < 8; k++) {
                __half2 w2h = __half2half2(
                    __ushort_as_half((unsigned short)(vv[k] & 0x7fffu)));
                bool neg = (vv[k] & 0x8000u) != 0;
                __half2 t0h = __hsub2(ps[0], *(__half2*)&pbv[k].x);
                __half2 t1h = __hsub2(ps[1], *(__half2*)&pbv[k].y);
                __half2 t2h = __hsub2(ps[2], *(__half2*)&pbv[k].z);
                __half2 t3h = __hsub2(ps[3], *(__half2*)&pbv[k].w);
                __half2 d0 = neg ? __hmin2(t0h, zero2) : __hmax2(t0h, zero2);
                __half2 d1 = neg ? __hmin2(t1h, zero2) : __hmax2(t1h, zero2);
                __half2 d2 = neg ? __hmin2(t2h, zero2) : __hmax2(t2h, zero2);
                __half2 d3 = neg ? __hmin2(t3h, zero2) : __hmax2(t3h, zero2);
                acc[0] = __hfma2(d0, w2h, acc[0]);
                acc[1] = __hfma2(d1, w2h, acc[1]);
                acc[2] = __hfma2(d2, w2h, acc[2]);
                acc[3] = __hfma2(d3, w2h, acc[3]);
            }
        }
    }

    // stage partials
#pragma unroll
    for (int i = 0; i < 4; i++) {
        float2 f = __half22float2(acc[i]);
        *(float2*)&sS[pair][halfId][gi][li * 8 + 2 * i] = f;
    }
    // pair barrier (64 threads, ids 1..4)
    asm volatile("bar.sync %0, 64;" :: "r"(1 + pair) : "memory");

    // epilogue: even warp -> nodes 0,1 ; odd warp -> nodes 2,3
    int o0 = 2 * lane;
#pragma unroll
    for (int m = 0; m < 2; m++) {
        int localn = halfId * 2 + m;
        int nq = nBase + localn;
        if (nq >= nN) break;
        const float* s0 = sS[pair][0][localn];
        const float* s1 = sS[pair][1][localn];
        float y0 = 0.f, y1 = 0.f;
#pragma unroll 8
        for (int k = 0; k < 64; k++) {
            float sk = s0[k] + s1[k];
            float2 av = __half22float2(*(const __half2*)&sKy[k * 66 + o0]);
            y0 += av.x * sk;
            y1 += av.y * sk;
        }
        size_t off = (size_t)nq * NOPEN + o0;
        float2 xv = *(const float2*)&g_x[off];
        xv.x -= DTH * y0;
        xv.y -= DTH * y1;

        __syncwarp();
        // stage x into this warp's own partial slot (done reading it)
        float* xs = sS[pair][halfId][localn];
        xs[o0] = xv.x; xs[o0 + 1] = xv.y;
        __syncwarp();
        float v0 = 0.f, v1 = 0.f;
#pragma unroll 8
        for (int k = 0; k < 64; k++) {
            float xk = xs[k];
            float2 av = __half22float2(*(const __half2*)&sKp[k * 66 + o0]);
            v0 += av.x * xk;
            v1 += av.y * xk;
        }

        if (!last) {
            *(float2*)&g_x[off] = xv;
            pout[(size_t)nq * 32 + lane] = __floats2half2_rn(v0, v1);
        } else {
            float mx = fmaxf(v0, v1);
#pragma unroll
            for (int o = 16; o; o >>= 1)
                mx = fmaxf(mx, __shfl_xor_sync(0xffffffffu, mx, o));
            float s = expf(v0 - mx) + expf(v1 - mx);
#pragma unroll
            for (int o = 16; o; o >>= 1)
                s += __shfl_xor_sync(0xffffffffu, s, o);
            float lse = mx + logf(s);
            float2 r;
            r.x = v0 - lse;
            r.y = v1 - lse;
            *(float2*)&out[(size_t)nq * NOPEN + o0] = r;
        }
        __syncwarp();
    }
}

// ---------------- launch ----------------
extern "C" void kernel_launch(void* const* d_in, const int* in_sizes, int n_in,
                              void* d_out, int out_size) {
    const float* xn   = (const float*)d_in[0];
    const int*   iInd = (const int*)d_in[1];
    const int*   jInd = (const int*)d_in[2];
    int base = 3;
    if (n_in >= 7 && in_sizes[3] == 1) base = 4;
    const float* K1  = (const float*)d_in[base];
    const float* KN1 = (const float*)d_in[base + 1];
    const float* KC  = (const float*)d_in[base + 2];

    int nN = in_sizes[0] / NNIN;
    int nE = in_sizes[1];

    int nodeBlocks8 = (nN + 7) / 8;
    int layerBlocks = (nN + 15) / 16;        // 16 nodes per block (4 quads)
    int nb256 = (nN + 255) / 256;
    int eb256 = (nE + 255) / 256;
    int nPad4 = (nN + 3) / 4;
    int scanBlocks = (nPad4 + SCAN_B - 1) / SCAN_B;

    // CSR build + norm
    init_x0_kernel<<<nb256, 256>>>(xn, K1, nN);
    count_kernel<<<eb256, 256>>>(iInd, jInd, nE);
    scanA_kernel<<<scanBlocks, SCAN_B>>>(nPad4, nN);
    scanB_kernel<<<1, 256>>>(scanBlocks);
    scanC_kernel<<<scanBlocks, SCAN_B>>>(nPad4);
    fill_kernel<<<eb256, 256>>>(iInd, jInd, nE);

    // network
    pre_kernel<<<nodeBlocks8, 256>>>(KN1, nN);
    for (int l = 0; l < 4; l++)
        layer_kernel<<<layerBlocks, 256>>>(KN1, KC, (float*)d_out, nN, l & 1,
                                           l == 3 ? 1 : 0);
}